// round 3
// baseline (speedup 1.0000x reference)
#include <cuda_runtime.h>

#define NN 8
#define CIN 256
#define LTOT 3136
#define CH 128
#define GG 8
#define HH 56
#define NB 448          // NN*56
#define QC 256
#define RELW 111

// ---------------- device scratch (static, no allocation) ----------------
__device__ float g_featA[NN * CH * LTOT];   // 12.8 MB
__device__ float g_featB[NN * CH * LTOT];   // 12.8 MB
__device__ float g_qkv[NB * QC * HH];       // 25.7 MB (== 8*256*3136, reused for conv_up out)
__device__ float g_so[NB * QC * HH];        // 25.7 MB
__device__ float g_cA[QC];                  // folded BN scale (stage-sequential reuse)
__device__ float g_cB[QC];                  // folded BN shift
__device__ float g_sstat[48];               // sim BN stats (24 ch x {sum,sumsq})
__device__ float g_scoef[GG * 4];           // per group {a_qk, a_qr, a_kr, bias}

// ---------------- helpers ----------------
__device__ __forceinline__ float fast_exp(float x) {
    float y = x * 1.4426950408889634f;
    y = fmaxf(y, -120.0f);
    float n = floorf(y);
    float f = y - n;
    float p = 1.8775767e-3f;
    p = fmaf(p, f, 8.9893397e-3f);
    p = fmaf(p, f, 5.5826318e-2f);
    p = fmaf(p, f, 2.4015361e-1f);
    p = fmaf(p, f, 6.9315308e-1f);
    p = fmaf(p, f, 9.9999994e-1f);
    return p * __int_as_float(((int)n + 127) << 23);
}

// ---------------- grouped conv down: (8,256,3136) -> (8,128,3136) raw ----------------
__global__ __launch_bounds__(224) void k_conv_down(const float* __restrict__ x,
                                                   const float* __restrict__ w,
                                                   float* __restrict__ out) {
    __shared__ float sW[16][32];
    int lt = blockIdx.x % 14;
    int g  = (blockIdx.x / 14) % GG;
    int n  = blockIdx.x / (14 * GG);
    int t = threadIdx.x;
    for (int i = t; i < 512; i += 224) sW[i >> 5][i & 31] = w[(g * 16) * 32 + i];
    __syncthreads();
    int l = lt * 224 + t;
    float acc[16];
#pragma unroll
    for (int o = 0; o < 16; o++) acc[o] = 0.f;
    const float* xp = x + ((size_t)(n * CIN + g * 32)) * LTOT + l;
#pragma unroll 8
    for (int k = 0; k < 32; k++) {
        float xv = xp[(size_t)k * LTOT];
#pragma unroll
        for (int o = 0; o < 16; o++) acc[o] = fmaf(sW[o][k], xv, acc[o]);
    }
    float* op = out + ((size_t)(n * CH + g * 16)) * LTOT + l;
#pragma unroll
    for (int o = 0; o < 16; o++) op[(size_t)o * LTOT] = acc[o];
}

// ---------------- per-channel BN stats -> folded coefficients ----------------
__global__ __launch_bounds__(256) void k_stats(const float* __restrict__ data,
                                               int outer, int nch, int inner,
                                               const float* __restrict__ gamma,
                                               const float* __restrict__ beta) {
    int ch = blockIdx.x;
    int t = threadIdx.x;
    int cnt = outer * inner;
    float s1 = 0.f, s2 = 0.f;
    for (int i = t; i < cnt; i += 256) {
        int o = i / inner, k = i - o * inner;
        float v = data[((size_t)o * nch + ch) * inner + k];
        s1 += v; s2 += v * v;
    }
    __shared__ float r1[8], r2[8];
    int lane = t & 31, wp = t >> 5;
#pragma unroll
    for (int off = 16; off; off >>= 1) {
        s1 += __shfl_xor_sync(~0u, s1, off);
        s2 += __shfl_xor_sync(~0u, s2, off);
    }
    if (lane == 0) { r1[wp] = s1; r2[wp] = s2; }
    __syncthreads();
    if (t == 0) {
        float a1 = 0.f, a2 = 0.f;
        for (int i = 0; i < 8; i++) { a1 += r1[i]; a2 += r2[i]; }
        float m = a1 / (float)cnt;
        float var = a2 / (float)cnt - m * m;
        float a = gamma[ch] * rsqrtf(var + 1e-5f);
        g_cA[ch] = a;
        g_cB[ch] = beta[ch] - m * a;
    }
}

// ---------------- QKV GEMM per b-row: qkv[b,o,h] = sum_c W[o,c]*f(src) ----------------
__global__ __launch_bounds__(256) void k_qkv(const float* __restrict__ src,
                                             const float* __restrict__ W,
                                             float* __restrict__ qkv,
                                             int prox, int useBN) {
    __shared__ float sX[128][57];
    __shared__ float sW[16][257];
    int b = blockIdx.x;
    int n = b / HH, wpos = b % HH;
    int t = threadIdx.x;
    for (int i = t; i < CH * HH; i += 256) {
        int c = i / HH, h = i - c * HH;
        size_t idx = prox ? (((size_t)(n * CH + c) * HH + wpos) * HH + h)
                          : (((size_t)(n * CH + c) * HH + h) * HH + wpos);
        float v = src[idx];
        if (useBN) { v = fmaf(v, g_cA[c], g_cB[c]); v = fmaxf(v, 0.f); }
        sX[c][h] = v;
    }
    int o0 = t & 31;
    int h0 = (t >> 5) * 7;
    float acc[8][7];
#pragma unroll
    for (int m = 0; m < 8; m++)
#pragma unroll
        for (int u = 0; u < 7; u++) acc[m][u] = 0.f;

    for (int cc = 0; cc < 128; cc += 16) {
        __syncthreads();
        for (int i = t; i < 4096; i += 256) {
            int o = i >> 4, j = i & 15;
            sW[j][o] = W[o * 128 + cc + j];
        }
        __syncthreads();
#pragma unroll
        for (int j = 0; j < 16; j++) {
            int c = cc + j;
            float xv[7];
#pragma unroll
            for (int u = 0; u < 7; u++) xv[u] = sX[c][h0 + u];
#pragma unroll
            for (int m = 0; m < 8; m++) {
                float wv = sW[j][o0 + 32 * m];
#pragma unroll
                for (int u = 0; u < 7; u++) acc[m][u] = fmaf(wv, xv[u], acc[m][u]);
            }
        }
    }
    // stage output through smem for coalesced global writes
    float* sOut = &sX[0][0];
#pragma unroll
    for (int half = 0; half < 2; half++) {
        __syncthreads();
#pragma unroll
        for (int m = 0; m < 4; m++) {
            int mm = m + 4 * half;
            int orow = o0 + 32 * m;  // row within this 128-half
#pragma unroll
            for (int u = 0; u < 7; u++) sOut[orow * 57 + h0 + u] = acc[mm][u];
        }
        __syncthreads();
        float* dst = qkv + (size_t)b * (QC * HH) + half * 128 * HH;
        for (int i = t; i < 128 * HH; i += 256) {
            int o = i / HH, h = i - o * HH;
            dst[i] = sOut[o * 57 + h];
        }
    }
}

// ---------------- sim BN stats: accumulate sum/sumsq of qk,qr,kr per (part,g) --------
__global__ void k_clear48() { if (threadIdx.x < 48) g_sstat[threadIdx.x] = 0.f; }

__global__ __launch_bounds__(224) void k_simstats(const float* __restrict__ qkv,
                                                  const float* __restrict__ rel) {
    __shared__ float sQ[8][57], sK[8][57];
    __shared__ float sQE[8][112], sKE[8][112];
    __shared__ float red[7][6];
    int g = blockIdx.x & 7;
    int b = blockIdx.x >> 3;
    int t = threadIdx.x;
    const float* base = qkv + (size_t)b * (QC * HH) + g * 32 * HH;
    for (int i = t; i < 16 * HH; i += 224) {
        int c = i / HH, h = i - c * HH;
        int o = g * 32 + c;
        float v = fmaf(base[c * HH + h], g_cA[o], g_cB[o]);
        if (c < 8) sQ[c][h] = v; else sK[c - 8][h] = v;
    }
    for (int i = t; i < 16 * RELW; i += 224) {
        int c = i / RELW, d = i - c * RELW;
        float v = rel[c * RELW + d];
        if (c < 8) sQE[c][d] = v; else sKE[c - 8][d] = v;
    }
    __syncthreads();
    int i0 = t >> 2, jt = t & 3;
    float qv[8];
#pragma unroll
    for (int c = 0; c < 8; c++) qv[c] = sQ[c][i0];
    float s0 = 0.f, q0 = 0.f, s1 = 0.f, q1 = 0.f, s2 = 0.f, q2 = 0.f;
#pragma unroll
    for (int u = 0; u < 14; u++) {
        int j = jt * 14 + u;
        int d1 = i0 - j + 55, d2 = 110 - d1;
        float qk = 0.f, qr = 0.f, kr = 0.f;
#pragma unroll
        for (int c = 0; c < 8; c++) {
            float kj = sK[c][j];
            qk = fmaf(qv[c], kj, qk);
            qr = fmaf(qv[c], sQE[c][d1], qr);
            kr = fmaf(kj, sKE[c][d2], kr);
        }
        s0 += qk; q0 += qk * qk;
        s1 += qr; q1 += qr * qr;
        s2 += kr; q2 += kr * kr;
    }
    int lane = t & 31, wp = t >> 5;
#pragma unroll
    for (int off = 16; off; off >>= 1) {
        s0 += __shfl_xor_sync(~0u, s0, off); q0 += __shfl_xor_sync(~0u, q0, off);
        s1 += __shfl_xor_sync(~0u, s1, off); q1 += __shfl_xor_sync(~0u, q1, off);
        s2 += __shfl_xor_sync(~0u, s2, off); q2 += __shfl_xor_sync(~0u, q2, off);
    }
    if (lane == 0) {
        red[wp][0] = s0; red[wp][1] = q0; red[wp][2] = s1;
        red[wp][3] = q1; red[wp][4] = s2; red[wp][5] = q2;
    }
    __syncthreads();
    if (t == 0) {
        float a[6] = {0, 0, 0, 0, 0, 0};
        for (int w = 0; w < 7; w++)
            for (int q = 0; q < 6; q++) a[q] += red[w][q];
        atomicAdd(&g_sstat[(0 * 8 + g) * 2 + 0], a[0]);
        atomicAdd(&g_sstat[(0 * 8 + g) * 2 + 1], a[1]);
        atomicAdd(&g_sstat[(1 * 8 + g) * 2 + 0], a[2]);
        atomicAdd(&g_sstat[(1 * 8 + g) * 2 + 1], a[3]);
        atomicAdd(&g_sstat[(2 * 8 + g) * 2 + 0], a[4]);
        atomicAdd(&g_sstat[(2 * 8 + g) * 2 + 1], a[5]);
    }
}

__global__ void k_simcoef(const float* __restrict__ gamma, const float* __restrict__ beta) {
    __shared__ float sa[24], sb[24];
    int t = threadIdx.x;
    if (t < 24) {
        float cnt = 448.f * 3136.f;
        float m = g_sstat[t * 2] / cnt;
        float var = g_sstat[t * 2 + 1] / cnt - m * m;
        float a = gamma[t] * rsqrtf(var + 1e-5f);
        sa[t] = a; sb[t] = beta[t] - m * a;
    }
    __syncthreads();
    if (t < 8) {
        g_scoef[t * 4 + 0] = sa[t];
        g_scoef[t * 4 + 1] = sa[8 + t];
        g_scoef[t * 4 + 2] = sa[16 + t];
        g_scoef[t * 4 + 3] = sb[t] + sb[8 + t] + sb[16 + t];
    }
}

// ---------------- fused attention per (b,g): logits -> softmax -> sv/sve -------------
__global__ __launch_bounds__(224) void k_attn(const float* __restrict__ qkv,
                                              const float* __restrict__ rel,
                                              float* __restrict__ so) {
    __shared__ float sQ[8][57], sK[8][57], sV[16][57];
    __shared__ float sQE[8][112], sKE[8][112], sVE[16][112];
    __shared__ float sSim[56][57];
    __shared__ float sInv[56];
    int g = blockIdx.x & 7;
    int b = blockIdx.x >> 3;
    int t = threadIdx.x;
    const float* base = qkv + (size_t)b * (QC * HH) + g * 32 * HH;
    for (int i = t; i < 32 * HH; i += 224) {
        int c = i / HH, h = i - c * HH;
        int o = g * 32 + c;
        float v = fmaf(base[c * HH + h], g_cA[o], g_cB[o]);
        if (c < 8) sQ[c][h] = v;
        else if (c < 16) sK[c - 8][h] = v;
        else sV[c - 16][h] = v;
    }
    for (int i = t; i < 32 * RELW; i += 224) {
        int c = i / RELW, d = i - c * RELW;
        float v = rel[c * RELW + d];
        if (c < 8) sQE[c][d] = v;
        else if (c < 16) sKE[c - 8][d] = v;
        else sVE[c - 16][d] = v;
    }
    __syncthreads();
    float aqk = g_scoef[g * 4 + 0], aqr = g_scoef[g * 4 + 1];
    float akr = g_scoef[g * 4 + 2], bias = g_scoef[g * 4 + 3];
    int i0 = t >> 2, jt = t & 3;
    float qv[8];
#pragma unroll
    for (int c = 0; c < 8; c++) qv[c] = sQ[c][i0];
    float lg[14];
#pragma unroll
    for (int u = 0; u < 14; u++) {
        int j = jt * 14 + u;
        int d1 = i0 - j + 55, d2 = 110 - d1;
        float qk = 0.f, qr = 0.f, kr = 0.f;
#pragma unroll
        for (int c = 0; c < 8; c++) {
            float kj = sK[c][j];
            qk = fmaf(qv[c], kj, qk);
            qr = fmaf(qv[c], sQE[c][d1], qr);
            kr = fmaf(kj, sKE[c][d2], kr);
        }
        lg[u] = fmaf(aqk, qk, fmaf(aqr, qr, fmaf(akr, kr, bias)));
    }
    // softmax over row i0 (4 threads cooperate, lanes 4a..4a+3 share i0)
    float m = -1e30f;
#pragma unroll
    for (int u = 0; u < 14; u++) m = fmaxf(m, lg[u]);
    m = fmaxf(m, __shfl_xor_sync(~0u, m, 1));
    m = fmaxf(m, __shfl_xor_sync(~0u, m, 2));
    float s = 0.f;
#pragma unroll
    for (int u = 0; u < 14; u++) { lg[u] = fast_exp(lg[u] - m); s += lg[u]; }
    s += __shfl_xor_sync(~0u, s, 1);
    s += __shfl_xor_sync(~0u, s, 2);
#pragma unroll
    for (int u = 0; u < 14; u++) sSim[i0][jt * 14 + u] = lg[u];
    if (jt == 0) sInv[i0] = 1.f / s;
    __syncthreads();
    // phase 3: sv/sve. thread owns 4 channels x 1 row
    int c4 = t / 56, ii = t % 56;
    float asv[4], asve[4];
#pragma unroll
    for (int z = 0; z < 4; z++) { asv[z] = 0.f; asve[z] = 0.f; }
    for (int j = 0; j < 56; j++) {
        float e = sSim[ii][j];
        int d = ii - j + 55;
#pragma unroll
        for (int z = 0; z < 4; z++) {
            int c = c4 * 4 + z;
            asv[z] = fmaf(e, sV[c][j], asv[z]);
            asve[z] = fmaf(e, sVE[c][d], asve[z]);
        }
    }
    float inv = sInv[ii];
    float* ob = so + (size_t)b * (QC * HH) + (g * 32) * HH + ii;
#pragma unroll
    for (int z = 0; z < 4; z++) {
        int c = c4 * 4 + z;
        ob[(2 * c) * HH] = asv[z] * inv;
        ob[(2 * c + 1) * HH] = asve[z] * inv;
    }
}

// ---------------- bn_out apply + pair sum + transpose back to (N,C,A,B) --------------
__global__ __launch_bounds__(256) void k_recombine(const float* __restrict__ so,
                                                   float* __restrict__ dst, int prox) {
    int idx = blockIdx.x * 256 + threadIdx.x;
    if (idx >= NB * CH * HH) return;
    int h = idx % HH;
    int cc = (idx / HH) % CH;
    int row = idx / (HH * CH);
    int o = 2 * cc;
    float v = fmaf(so[(size_t)row * (QC * HH) + o * HH + h], g_cA[o], g_cB[o]) +
              fmaf(so[(size_t)row * (QC * HH) + (o + 1) * HH + h], g_cA[o + 1], g_cB[o + 1]);
    int n = row / HH, wpos = row % HH;
    size_t di = prox ? (((size_t)(n * CH + cc) * HH + wpos) * HH + h)
                     : (((size_t)(n * CH + cc) * HH + h) * HH + wpos);
    dst[di] = v;
}

// ---------------- grouped conv up: relu(h) -> (8,256,3136) raw -----------------------
__global__ __launch_bounds__(224) void k_conv_up(const float* __restrict__ hbuf,
                                                 const float* __restrict__ w,
                                                 float* __restrict__ out) {
    __shared__ float sW[32][16];
    int lt = blockIdx.x % 14;
    int g  = (blockIdx.x / 14) % GG;
    int n  = blockIdx.x / (14 * GG);
    int t = threadIdx.x;
    for (int i = t; i < 512; i += 224) sW[i >> 4][i & 15] = w[(g * 32) * 16 + i];
    __syncthreads();
    int l = lt * 224 + t;
    float acc[32];
#pragma unroll
    for (int o = 0; o < 32; o++) acc[o] = 0.f;
    const float* hp = hbuf + ((size_t)(n * CH + g * 16)) * LTOT + l;
#pragma unroll 4
    for (int k = 0; k < 16; k++) {
        float hv = fmaxf(hp[(size_t)k * LTOT], 0.f);
#pragma unroll
        for (int o = 0; o < 32; o++) acc[o] = fmaf(sW[o][k], hv, acc[o]);
    }
    float* op = out + ((size_t)(n * CIN + g * 32)) * LTOT + l;
#pragma unroll
    for (int o = 0; o < 32; o++) op[(size_t)o * LTOT] = acc[o];
}

// ---------------- final: relu(x + bn2(conv_up) * rw) ---------------------------------
__global__ __launch_bounds__(256) void k_final(const float* __restrict__ x,
                                               const float* __restrict__ cu,
                                               const float* __restrict__ rw,
                                               float* __restrict__ out) {
    int idx = blockIdx.x * 256 + threadIdx.x;
    if (idx >= NN * CIN * LTOT) return;
    int ch = (idx / LTOT) & 255;
    float v = fmaf(fmaf(cu[idx], g_cA[ch], g_cB[ch]), __ldg(rw), x[idx]);
    out[idx] = fmaxf(v, 0.f);
}

// ---------------- launch ----------------
extern "C" void kernel_launch(void* const* d_in, const int* in_sizes, int n_in,
                              void* d_out, int out_size) {
    const float* x    = (const float*)d_in[0];
    const float* cdw  = (const float*)d_in[1];
    const float* bn1g = (const float*)d_in[2];
    const float* bn1b = (const float*)d_in[3];
    const float* qkvw = (const float*)d_in[4];
    const float* bqg  = (const float*)d_in[5];
    const float* bqb  = (const float*)d_in[6];
    const float* bsg  = (const float*)d_in[7];
    const float* bsb  = (const float*)d_in[8];
    const float* bog  = (const float*)d_in[9];
    const float* bob  = (const float*)d_in[10];
    const float* rel  = (const float*)d_in[11];
    const float* cuw  = (const float*)d_in[12];
    const float* bn2g = (const float*)d_in[13];
    const float* bn2b = (const float*)d_in[14];
    const float* rw   = (const float*)d_in[15];
    float* out = (float*)d_out;

    float *fA, *fB, *qk, *so;
    cudaGetSymbolAddress((void**)&fA, g_featA);
    cudaGetSymbolAddress((void**)&fB, g_featB);
    cudaGetSymbolAddress((void**)&qk, g_qkv);
    cudaGetSymbolAddress((void**)&so, g_so);

    k_conv_down<<<896, 224>>>(x, cdw, fA);
    k_stats<<<128, 256>>>(fA, 8, 128, 3136, bn1g, bn1b);

    const float* srcs[3] = {fA, fB, fA};
    float* dsts[3]       = {fB, fA, fB};
    const int proxs[3]   = {1, 0, 1};
    for (int i = 0; i < 3; i++) {
        k_qkv<<<448, 256>>>(srcs[i], qkvw + i * QC * CH, qk, proxs[i], i == 0 ? 1 : 0);
        k_stats<<<256, 256>>>(qk, 448, 256, 56, bqg + i * 256, bqb + i * 256);
        k_clear48<<<1, 64>>>();
        k_simstats<<<3584, 224>>>(qk, rel + i * 32 * RELW);
        k_simcoef<<<1, 32>>>(bsg + i * 24, bsb + i * 24);
        k_attn<<<3584, 224>>>(qk, rel + i * 32 * RELW, so);
        k_stats<<<256, 256>>>(so, 448, 256, 56, bog + i * 256, bob + i * 256);
        k_recombine<<<12544, 256>>>(so, dsts[i], proxs[i]);
    }

    k_conv_up<<<896, 224>>>(fB, cuw, qk);
    k_stats<<<256, 256>>>(qk, 8, 256, 3136, bn2g, bn2b);
    k_final<<<25088, 256>>>(x, qk, rw, out);
}

// round 4
// speedup vs baseline: 1.1716x; 1.1716x over previous
#include <cuda_runtime.h>

#define NN 8
#define CIN 256
#define LTOT 3136
#define CH 128
#define GG 8
#define HH 56
#define NB 448          // NN*56
#define QC 256
#define RELW 111

// ---------------- device scratch (static, no allocation) ----------------
__device__ float g_featA[NN * CH * LTOT];   // 12.8 MB
__device__ float g_featB[NN * CH * LTOT];   // 12.8 MB
__device__ float g_qkv[NB * QC * HH];       // 25.7 MB (reused for conv_up out)
__device__ float g_so[NB * QC * HH];        // 25.7 MB
__device__ float g_cA[QC];                  // folded BN scale (stage-sequential reuse)
__device__ float g_cB[QC];                  // folded BN shift
__device__ float g_stat[2 * QC];            // per-channel {sum,sumsq} accumulators
__device__ float g_sstat[48];               // sim BN stats (24 ch x {sum,sumsq})
__device__ float g_scoef[GG * 4];           // per group {a_qk, a_qr, a_kr, bias}

// ---------------- helpers ----------------
__device__ __forceinline__ float fast_exp(float x) {
    float y = x * 1.4426950408889634f;
    y = fmaxf(y, -120.0f);
    float n = floorf(y);
    float f = y - n;
    float p = 1.8775767e-3f;
    p = fmaf(p, f, 8.9893397e-3f);
    p = fmaf(p, f, 5.5826318e-2f);
    p = fmaf(p, f, 2.4015361e-1f);
    p = fmaf(p, f, 6.9315308e-1f);
    p = fmaf(p, f, 9.9999994e-1f);
    return p * __int_as_float(((int)n + 127) << 23);
}

__global__ void k_zerostat() {
    int t = threadIdx.x;
    if (t < 512) g_stat[t] = 0.f;
    if (t < 48) g_sstat[t] = 0.f;
}

// coef: fold accumulated stats into (a,b); zero accumulators for next stage.
__global__ void k_coef(const float* __restrict__ gamma, const float* __restrict__ beta,
                       int nch, int clearSim) {
    int ch = threadIdx.x;
    if (ch < nch) {
        const float invc = 1.f / 25088.f;   // count = 25088 for every BN in this net
        float m = g_stat[2 * ch] * invc;
        float var = g_stat[2 * ch + 1] * invc - m * m;
        float a = gamma[ch] * rsqrtf(var + 1e-5f);
        g_cA[ch] = a;
        g_cB[ch] = beta[ch] - m * a;
        g_stat[2 * ch] = 0.f;
        g_stat[2 * ch + 1] = 0.f;
    }
    if (clearSim && ch < 48) g_sstat[ch] = 0.f;
}

// ---------------- grouped conv down + fused bn1 stats ----------------
__global__ __launch_bounds__(224) void k_conv_down(const float* __restrict__ x,
                                                   const float* __restrict__ w,
                                                   float* __restrict__ out) {
    __shared__ float sW[16][32];
    __shared__ float sRs[7][16], sRq[7][16];
    int lt = blockIdx.x % 14;
    int g  = (blockIdx.x / 14) % GG;
    int n  = blockIdx.x / (14 * GG);
    int t = threadIdx.x;
    for (int i = t; i < 512; i += 224) sW[i >> 5][i & 31] = w[(g * 16) * 32 + i];
    __syncthreads();
    int l = lt * 224 + t;
    float acc[16];
#pragma unroll
    for (int o = 0; o < 16; o++) acc[o] = 0.f;
    const float* xp = x + ((size_t)(n * CIN + g * 32)) * LTOT + l;
#pragma unroll 8
    for (int k = 0; k < 32; k++) {
        float xv = xp[(size_t)k * LTOT];
#pragma unroll
        for (int o = 0; o < 16; o++) acc[o] = fmaf(sW[o][k], xv, acc[o]);
    }
    float* op = out + ((size_t)(n * CH + g * 16)) * LTOT + l;
#pragma unroll
    for (int o = 0; o < 16; o++) op[(size_t)o * LTOT] = acc[o];
    // fused per-channel stats
    int lane = t & 31, wp = t >> 5;
#pragma unroll
    for (int o = 0; o < 16; o++) {
        float v = acc[o], v2 = v * v;
#pragma unroll
        for (int off = 16; off; off >>= 1) {
            v += __shfl_xor_sync(~0u, v, off);
            v2 += __shfl_xor_sync(~0u, v2, off);
        }
        if (lane == 0) { sRs[wp][o] = v; sRq[wp][o] = v2; }
    }
    __syncthreads();
    if (t < 16) {
        float a1 = 0.f, a2 = 0.f;
#pragma unroll
        for (int w2 = 0; w2 < 7; w2++) { a1 += sRs[w2][t]; a2 += sRq[w2][t]; }
        atomicAdd(&g_stat[(g * 16 + t) * 2], a1);
        atomicAdd(&g_stat[(g * 16 + t) * 2 + 1], a2);
    }
}

// ---------------- QKV GEMM per b-row + fused bn_qkv stats ----------------
__global__ __launch_bounds__(256) void k_qkv(const float* __restrict__ src,
                                             const float* __restrict__ W,
                                             float* __restrict__ qkv,
                                             int prox, int useBN) {
    __shared__ float sX[128][57];
    __shared__ float sW[16][257];     // 4112 floats; reused as stats scratch
    int b = blockIdx.x;
    int n = b / HH, wpos = b % HH;
    int t = threadIdx.x;
    for (int i = t; i < CH * HH; i += 256) {
        int c = i / HH, h = i - c * HH;
        size_t idx = prox ? (((size_t)(n * CH + c) * HH + wpos) * HH + h)
                          : (((size_t)(n * CH + c) * HH + h) * HH + wpos);
        float v = src[idx];
        if (useBN) { v = fmaf(v, g_cA[c], g_cB[c]); v = fmaxf(v, 0.f); }
        sX[c][h] = v;
    }
    int o0 = t & 31;
    int h0 = (t >> 5) * 7;
    float acc[8][7];
#pragma unroll
    for (int m = 0; m < 8; m++)
#pragma unroll
        for (int u = 0; u < 7; u++) acc[m][u] = 0.f;

    for (int cc = 0; cc < 128; cc += 16) {
        __syncthreads();
        for (int i = t; i < 4096; i += 256) {
            int o = i >> 4, j = i & 15;
            sW[j][o] = W[o * 128 + cc + j];
        }
        __syncthreads();
#pragma unroll
        for (int j = 0; j < 16; j++) {
            int c = cc + j;
            float xv[7];
#pragma unroll
            for (int u = 0; u < 7; u++) xv[u] = sX[c][h0 + u];
#pragma unroll
            for (int m = 0; m < 8; m++) {
                float wv = sW[j][o0 + 32 * m];
#pragma unroll
                for (int u = 0; u < 7; u++) acc[m][u] = fmaf(wv, xv[u], acc[m][u]);
            }
        }
    }
    // ---- fused stats: each warp covers all 256 channels over its 7 h ----
    __syncthreads();
    {
        float* scr = &sW[0][0];   // need 4096 floats
        int wp = t >> 5;
#pragma unroll
        for (int m = 0; m < 8; m++) {
            float s = 0.f, qq = 0.f;
#pragma unroll
            for (int u = 0; u < 7; u++) { float v = acc[m][u]; s += v; qq = fmaf(v, v, qq); }
            scr[wp * 256 + o0 + 32 * m] = s;
            scr[2048 + wp * 256 + o0 + 32 * m] = qq;
        }
        __syncthreads();
        float a1 = 0.f, a2 = 0.f;
#pragma unroll
        for (int w2 = 0; w2 < 8; w2++) {
            a1 += scr[w2 * 256 + t];
            a2 += scr[2048 + w2 * 256 + t];
        }
        atomicAdd(&g_stat[2 * t], a1);
        atomicAdd(&g_stat[2 * t + 1], a2);
    }
    // ---- stage output through smem for coalesced global writes ----
    float* sOut = &sX[0][0];
#pragma unroll
    for (int half = 0; half < 2; half++) {
        __syncthreads();
#pragma unroll
        for (int m = 0; m < 4; m++) {
            int mm = m + 4 * half;
            int orow = o0 + 32 * m;
#pragma unroll
            for (int u = 0; u < 7; u++) sOut[orow * 57 + h0 + u] = acc[mm][u];
        }
        __syncthreads();
        float* dst = qkv + (size_t)b * (QC * HH) + half * 128 * HH;
        for (int i = t; i < 128 * HH; i += 256) {
            int o = i / HH, h = i - o * HH;
            dst[i] = sOut[o * 57 + h];
        }
    }
}

// ---------------- sim BN stats: sum/sumsq of qk,qr,kr per (part,g) --------
__global__ __launch_bounds__(224) void k_simstats(const float* __restrict__ qkv,
                                                  const float* __restrict__ rel) {
    __shared__ float sQ[8][57], sK[8][57];
    __shared__ float sQE[8][112], sKE[8][112];
    __shared__ float red[7][6];
    int g = blockIdx.x & 7;
    int b = blockIdx.x >> 3;
    int t = threadIdx.x;
    const float* base = qkv + (size_t)b * (QC * HH) + g * 32 * HH;
    for (int i = t; i < 16 * HH; i += 224) {
        int c = i / HH, h = i - c * HH;
        int o = g * 32 + c;
        float v = fmaf(base[c * HH + h], g_cA[o], g_cB[o]);
        if (c < 8) sQ[c][h] = v; else sK[c - 8][h] = v;
    }
    for (int i = t; i < 16 * RELW; i += 224) {
        int c = i / RELW, d = i - c * RELW;
        float v = rel[c * RELW + d];
        if (c < 8) sQE[c][d] = v; else sKE[c - 8][d] = v;
    }
    __syncthreads();
    int i0 = t >> 2, jt = t & 3;
    float qv[8];
#pragma unroll
    for (int c = 0; c < 8; c++) qv[c] = sQ[c][i0];
    float s0 = 0.f, q0 = 0.f, s1 = 0.f, q1 = 0.f, s2 = 0.f, q2 = 0.f;
#pragma unroll
    for (int u = 0; u < 14; u++) {
        int j = jt * 14 + u;
        int d1 = i0 - j + 55, d2 = 110 - d1;
        float qk = 0.f, qr = 0.f, kr = 0.f;
#pragma unroll
        for (int c = 0; c < 8; c++) {
            float kj = sK[c][j];
            qk = fmaf(qv[c], kj, qk);
            qr = fmaf(qv[c], sQE[c][d1], qr);
            kr = fmaf(kj, sKE[c][d2], kr);
        }
        s0 += qk; q0 += qk * qk;
        s1 += qr; q1 += qr * qr;
        s2 += kr; q2 += kr * kr;
    }
    int lane = t & 31, wp = t >> 5;
#pragma unroll
    for (int off = 16; off; off >>= 1) {
        s0 += __shfl_xor_sync(~0u, s0, off); q0 += __shfl_xor_sync(~0u, q0, off);
        s1 += __shfl_xor_sync(~0u, s1, off); q1 += __shfl_xor_sync(~0u, q1, off);
        s2 += __shfl_xor_sync(~0u, s2, off); q2 += __shfl_xor_sync(~0u, q2, off);
    }
    if (lane == 0) {
        red[wp][0] = s0; red[wp][1] = q0; red[wp][2] = s1;
        red[wp][3] = q1; red[wp][4] = s2; red[wp][5] = q2;
    }
    __syncthreads();
    if (t == 0) {
        float a[6] = {0, 0, 0, 0, 0, 0};
        for (int w = 0; w < 7; w++)
            for (int q = 0; q < 6; q++) a[q] += red[w][q];
        atomicAdd(&g_sstat[(0 * 8 + g) * 2 + 0], a[0]);
        atomicAdd(&g_sstat[(0 * 8 + g) * 2 + 1], a[1]);
        atomicAdd(&g_sstat[(1 * 8 + g) * 2 + 0], a[2]);
        atomicAdd(&g_sstat[(1 * 8 + g) * 2 + 1], a[3]);
        atomicAdd(&g_sstat[(2 * 8 + g) * 2 + 0], a[4]);
        atomicAdd(&g_sstat[(2 * 8 + g) * 2 + 1], a[5]);
    }
}

__global__ void k_simcoef(const float* __restrict__ gamma, const float* __restrict__ beta) {
    __shared__ float sa[24], sb[24];
    int t = threadIdx.x;
    if (t < 24) {
        float cnt = 448.f * 3136.f;
        float m = g_sstat[t * 2] / cnt;
        float var = g_sstat[t * 2 + 1] / cnt - m * m;
        float a = gamma[t] * rsqrtf(var + 1e-5f);
        sa[t] = a; sb[t] = beta[t] - m * a;
    }
    __syncthreads();
    if (t < 8) {
        g_scoef[t * 4 + 0] = sa[t];
        g_scoef[t * 4 + 1] = sa[8 + t];
        g_scoef[t * 4 + 2] = sa[16 + t];
        g_scoef[t * 4 + 3] = sb[t] + sb[8 + t] + sb[16 + t];
    }
}

// ---------------- fused attention + fused bn_out stats -------------------
__global__ __launch_bounds__(224) void k_attn(const float* __restrict__ qkv,
                                              const float* __restrict__ rel,
                                              float* __restrict__ so) {
    __shared__ float sQ[8][57], sK[8][57], sV[16][57];
    __shared__ float sQE[8][112], sKE[8][112], sVE[16][112];
    __shared__ float sSim[56][57];   // reused as stats scratch (needs 1792 floats)
    __shared__ float sInv[56];
    int g = blockIdx.x & 7;
    int b = blockIdx.x >> 3;
    int t = threadIdx.x;
    const float* base = qkv + (size_t)b * (QC * HH) + g * 32 * HH;
    for (int i = t; i < 32 * HH; i += 224) {
        int c = i / HH, h = i - c * HH;
        int o = g * 32 + c;
        float v = fmaf(base[c * HH + h], g_cA[o], g_cB[o]);
        if (c < 8) sQ[c][h] = v;
        else if (c < 16) sK[c - 8][h] = v;
        else sV[c - 16][h] = v;
    }
    for (int i = t; i < 32 * RELW; i += 224) {
        int c = i / RELW, d = i - c * RELW;
        float v = rel[c * RELW + d];
        if (c < 8) sQE[c][d] = v;
        else if (c < 16) sKE[c - 8][d] = v;
        else sVE[c - 16][d] = v;
    }
    __syncthreads();
    float aqk = g_scoef[g * 4 + 0], aqr = g_scoef[g * 4 + 1];
    float akr = g_scoef[g * 4 + 2], bias = g_scoef[g * 4 + 3];
    int i0 = t >> 2, jt = t & 3;
    float qv[8];
#pragma unroll
    for (int c = 0; c < 8; c++) qv[c] = sQ[c][i0];
    float lg[14];
#pragma unroll
    for (int u = 0; u < 14; u++) {
        int j = jt * 14 + u;
        int d1 = i0 - j + 55, d2 = 110 - d1;
        float qk = 0.f, qr = 0.f, kr = 0.f;
#pragma unroll
        for (int c = 0; c < 8; c++) {
            float kj = sK[c][j];
            qk = fmaf(qv[c], kj, qk);
            qr = fmaf(qv[c], sQE[c][d1], qr);
            kr = fmaf(kj, sKE[c][d2], kr);
        }
        lg[u] = fmaf(aqk, qk, fmaf(aqr, qr, fmaf(akr, kr, bias)));
    }
    float m = -1e30f;
#pragma unroll
    for (int u = 0; u < 14; u++) m = fmaxf(m, lg[u]);
    m = fmaxf(m, __shfl_xor_sync(~0u, m, 1));
    m = fmaxf(m, __shfl_xor_sync(~0u, m, 2));
    float s = 0.f;
#pragma unroll
    for (int u = 0; u < 14; u++) { lg[u] = fast_exp(lg[u] - m); s += lg[u]; }
    s += __shfl_xor_sync(~0u, s, 1);
    s += __shfl_xor_sync(~0u, s, 2);
#pragma unroll
    for (int u = 0; u < 14; u++) sSim[i0][jt * 14 + u] = lg[u];
    if (jt == 0) sInv[i0] = 1.f / s;
    __syncthreads();
    // phase 3: sv/sve. thread owns 4 channels x 1 row
    int c4 = t / 56, ii = t % 56;
    float asv[4], asve[4];
#pragma unroll
    for (int z = 0; z < 4; z++) { asv[z] = 0.f; asve[z] = 0.f; }
    for (int j = 0; j < 56; j++) {
        float e = sSim[ii][j];
        int d = ii - j + 55;
#pragma unroll
        for (int z = 0; z < 4; z++) {
            int c = c4 * 4 + z;
            asv[z] = fmaf(e, sV[c][j], asv[z]);
            asve[z] = fmaf(e, sVE[c][d], asve[z]);
        }
    }
    float inv = sInv[ii];
    float vals[8];
    float* ob = so + (size_t)b * (QC * HH) + (g * 32) * HH + ii;
#pragma unroll
    for (int z = 0; z < 4; z++) {
        int c = c4 * 4 + z;
        vals[z * 2 + 0] = asv[z] * inv;
        vals[z * 2 + 1] = asve[z] * inv;
        ob[(2 * c) * HH] = vals[z * 2 + 0];
        ob[(2 * c + 1) * HH] = vals[z * 2 + 1];
    }
    // ---- fused bn_out stats (reuse sSim as scratch) ----
    __syncthreads();
    {
        float* sRed = &sSim[0][0];
#pragma unroll
        for (int z = 0; z < 4; z++) {
            sRed[t * 8 + z * 2 + 0] = vals[z * 2 + 0];
            sRed[t * 8 + z * 2 + 1] = vals[z * 2 + 1];
        }
        __syncthreads();
        if (t < 32) {
            int c4r = t >> 3, z = (t >> 1) & 3, p = t & 1;
            int off = z * 2 + p;
            float a1 = 0.f, a2 = 0.f;
            for (int ii2 = 0; ii2 < 56; ii2++) {
                float v = sRed[(c4r * 56 + ii2) * 8 + off];
                a1 += v; a2 = fmaf(v, v, a2);
            }
            atomicAdd(&g_stat[2 * (g * 32 + t)], a1);
            atomicAdd(&g_stat[2 * (g * 32 + t) + 1], a2);
        }
    }
}

// ---------------- bn_out apply + pair sum, prox=1 (coalesced both sides) ----
__global__ __launch_bounds__(256) void k_recombine(const float* __restrict__ so,
                                                   float* __restrict__ dst) {
    int idx = blockIdx.x * 256 + threadIdx.x;
    if (idx >= NB * CH * HH) return;
    int h = idx % HH;
    int cc = (idx / HH) % CH;
    int row = idx / (HH * CH);
    int o = 2 * cc;
    float v = fmaf(so[(size_t)row * (QC * HH) + o * HH + h], g_cA[o], g_cB[o]) +
              fmaf(so[(size_t)row * (QC * HH) + (o + 1) * HH + h], g_cA[o + 1], g_cB[o + 1]);
    int n = row / HH, wpos = row % HH;
    dst[((size_t)(n * CH + cc) * HH + wpos) * HH + h] = v;
}

// ---------------- bn_out apply + pair sum, prox=0 (smem transpose) ----------
__global__ __launch_bounds__(256) void k_recombine_t(const float* __restrict__ so,
                                                     float* __restrict__ dst) {
    __shared__ float sT[56][57];
    int cc = blockIdx.x & 127;
    int n = blockIdx.x >> 7;
    int t = threadIdx.x;
    int o = 2 * cc;
    float a0 = g_cA[o], b0 = g_cB[o], a1 = g_cA[o + 1], b1 = g_cB[o + 1];
    const float* base = so + ((size_t)n * HH) * (QC * HH);
    for (int i = t; i < 56 * 56; i += 256) {
        int w = i / 56, h = i - w * 56;
        const float* r = base + (size_t)w * (QC * HH) + o * HH + h;
        sT[w][h] = fmaf(r[0], a0, b0) + fmaf(r[HH], a1, b1);
    }
    __syncthreads();
    float* d = dst + ((size_t)(n * CH + cc)) * LTOT;
    for (int i = t; i < 56 * 56; i += 256) {
        int a = i / 56, bb = i - a * 56;
        d[i] = sT[bb][a];
    }
}

// ---------------- grouped conv up + fused bn2 stats -----------------------
__global__ __launch_bounds__(224) void k_conv_up(const float* __restrict__ hbuf,
                                                 const float* __restrict__ w,
                                                 float* __restrict__ out) {
    __shared__ float sW[32][16];
    __shared__ float sRs[7][32], sRq[7][32];
    int lt = blockIdx.x % 14;
    int g  = (blockIdx.x / 14) % GG;
    int n  = blockIdx.x / (14 * GG);
    int t = threadIdx.x;
    for (int i = t; i < 512; i += 224) sW[i >> 4][i & 15] = w[(g * 32) * 16 + i];
    __syncthreads();
    int l = lt * 224 + t;
    float acc[32];
#pragma unroll
    for (int o = 0; o < 32; o++) acc[o] = 0.f;
    const float* hp = hbuf + ((size_t)(n * CH + g * 16)) * LTOT + l;
#pragma unroll 4
    for (int k = 0; k < 16; k++) {
        float hv = fmaxf(hp[(size_t)k * LTOT], 0.f);
#pragma unroll
        for (int o = 0; o < 32; o++) acc[o] = fmaf(sW[o][k], hv, acc[o]);
    }
    float* op = out + ((size_t)(n * CIN + g * 32)) * LTOT + l;
#pragma unroll
    for (int o = 0; o < 32; o++) op[(size_t)o * LTOT] = acc[o];
    // fused stats
    int lane = t & 31, wp = t >> 5;
#pragma unroll
    for (int o = 0; o < 32; o++) {
        float v = acc[o], v2 = v * v;
#pragma unroll
        for (int off = 16; off; off >>= 1) {
            v += __shfl_xor_sync(~0u, v, off);
            v2 += __shfl_xor_sync(~0u, v2, off);
        }
        if (lane == 0) { sRs[wp][o] = v; sRq[wp][o] = v2; }
    }
    __syncthreads();
    if (t < 32) {
        float a1 = 0.f, a2 = 0.f;
#pragma unroll
        for (int w2 = 0; w2 < 7; w2++) { a1 += sRs[w2][t]; a2 += sRq[w2][t]; }
        atomicAdd(&g_stat[(g * 32 + t) * 2], a1);
        atomicAdd(&g_stat[(g * 32 + t) * 2 + 1], a2);
    }
}

// ---------------- final: relu(x + bn2(conv_up) * rw), float4 --------------
__global__ __launch_bounds__(256) void k_final(const float4* __restrict__ x,
                                               const float4* __restrict__ cu,
                                               const float* __restrict__ rw,
                                               float4* __restrict__ out) {
    int idx = blockIdx.x * 256 + threadIdx.x;
    if (idx >= NN * CIN * (LTOT / 4)) return;
    int ch = (idx / (LTOT / 4)) & 255;
    float a = g_cA[ch], bb = g_cB[ch], wv = __ldg(rw);
    float4 c = cu[idx], xx = x[idx], r;
    r.x = fmaxf(fmaf(fmaf(c.x, a, bb), wv, xx.x), 0.f);
    r.y = fmaxf(fmaf(fmaf(c.y, a, bb), wv, xx.y), 0.f);
    r.z = fmaxf(fmaf(fmaf(c.z, a, bb), wv, xx.z), 0.f);
    r.w = fmaxf(fmaf(fmaf(c.w, a, bb), wv, xx.w), 0.f);
    out[idx] = r;
}

// ---------------- launch ----------------
extern "C" void kernel_launch(void* const* d_in, const int* in_sizes, int n_in,
                              void* d_out, int out_size) {
    const float* x    = (const float*)d_in[0];
    const float* cdw  = (const float*)d_in[1];
    const float* bn1g = (const float*)d_in[2];
    const float* bn1b = (const float*)d_in[3];
    const float* qkvw = (const float*)d_in[4];
    const float* bqg  = (const float*)d_in[5];
    const float* bqb  = (const float*)d_in[6];
    const float* bsg  = (const float*)d_in[7];
    const float* bsb  = (const float*)d_in[8];
    const float* bog  = (const float*)d_in[9];
    const float* bob  = (const float*)d_in[10];
    const float* rel  = (const float*)d_in[11];
    const float* cuw  = (const float*)d_in[12];
    const float* bn2g = (const float*)d_in[13];
    const float* bn2b = (const float*)d_in[14];
    const float* rw   = (const float*)d_in[15];
    float* out = (float*)d_out;

    float *fA, *fB, *qk, *so;
    cudaGetSymbolAddress((void**)&fA, g_featA);
    cudaGetSymbolAddress((void**)&fB, g_featB);
    cudaGetSymbolAddress((void**)&qk, g_qkv);
    cudaGetSymbolAddress((void**)&so, g_so);

    k_zerostat<<<1, 512>>>();
    k_conv_down<<<896, 224>>>(x, cdw, fA);
    k_coef<<<1, 256>>>(bn1g, bn1b, 128, 0);

    const float* srcs[3] = {fA, fB, fA};
    float* dsts[3]       = {fB, fA, fB};
    const int proxs[3]   = {1, 0, 1};
    for (int i = 0; i < 3; i++) {
        k_qkv<<<448, 256>>>(srcs[i], qkvw + i * QC * CH, qk, proxs[i], i == 0 ? 1 : 0);
        k_coef<<<1, 256>>>(bqg + i * 256, bqb + i * 256, 256, 1);
        k_simstats<<<3584, 224>>>(qk, rel + i * 32 * RELW);
        k_simcoef<<<1, 32>>>(bsg + i * 24, bsb + i * 24);
        k_attn<<<3584, 224>>>(qk, rel + i * 32 * RELW, so);
        k_coef<<<1, 256>>>(bog + i * 256, bob + i * 256, 256, 0);
        if (proxs[i]) k_recombine<<<12544, 256>>>(so, dsts[i]);
        else          k_recombine_t<<<1024, 256>>>(so, dsts[i]);
    }

    k_conv_up<<<896, 224>>>(fB, cuw, qk);
    k_coef<<<1, 256>>>(bn2g, bn2b, 256, 0);
    k_final<<<6272, 256>>>((const float4*)x, (const float4*)qk, rw, (float4*)out);
}